// round 10
// baseline (speedup 1.0000x reference)
#include <cuda_runtime.h>
#include <cuda_bf16.h>
#include <stdint.h>

// ---------------------------------------------------------------------------
// Scratch (__device__ globals — allocation-free rule). Zero-initialized at
// module load; the fast path re-establishes "g_off==0, g_ovf_n==0" at the end
// of every kernel_launch sequence (self-cleaning invariant).
// ---------------------------------------------------------------------------
#define MAX_NODES 65536
#define MAX_MSGS  (1 << 21)          // 2M rows
#define CAP       96                 // per-node slot capacity (Poisson(20) safe)

__device__ int g_off[MAX_NODES];             // per-node arrival count / cursor
__device__ int g_idx[MAX_NODES * CAP];       // slotted index table
__device__ int g_ovf[MAX_MSGS * 2];          // overflow (msg, id) pairs
__device__ int g_ovf_n;

__device__ __forceinline__ int load_id_mode(const void* ids, int i, int is64)
{
    return is64 ? (int)((const long long*)ids)[i] : ((const int*)ids)[i];
}

// ---------------------------------------------------------------------------
// Permutation: slot-based bucketing. Per-block dtype detection (shared flag),
// then 8 messages per thread with vectorized id loads.
// PRECONDITION: g_off[] == 0, g_ovf_n == 0 (restored by gather_kernel).
// ---------------------------------------------------------------------------
__device__ __forceinline__ void perm_one(int i, int id)
{
    int pos = atomicAdd(&g_off[id], 1);
    if (pos < CAP) {
        g_idx[id * CAP + pos] = i;
    } else {
        int o = atomicAdd(&g_ovf_n, 1);
        g_ovf[o * 2 + 0] = i;
        g_ovf[o * 2 + 1] = id;
    }
}

__global__ void perm_kernel(const void* __restrict__ ids, int n)
{
    __shared__ int s_is64;
    if (threadIdx.x == 0) {
        const int* ids32 = (const int*)ids;
        int all_zero = 1;
        #pragma unroll 8
        for (int i = 1; i < 128; i += 2)
            if (ids32[i] != 0) { all_zero = 0; break; }
        s_is64 = all_zero;
    }
    __syncthreads();
    int is64 = s_is64;

    int base = (blockIdx.x * blockDim.x + threadIdx.x) * 8;
    if (base >= n) return;

    int idv[8];
    if (base + 8 <= n) {
        if (is64) {
            const longlong2* p = (const longlong2*)((const long long*)ids + base);
            longlong2 a = p[0], b = p[1], c = p[2], d = p[3];
            idv[0] = (int)a.x; idv[1] = (int)a.y;
            idv[2] = (int)b.x; idv[3] = (int)b.y;
            idv[4] = (int)c.x; idv[5] = (int)c.y;
            idv[6] = (int)d.x; idv[7] = (int)d.y;
        } else {
            const int4* p = (const int4*)((const int*)ids + base);
            int4 a = p[0], b = p[1];
            idv[0] = a.x; idv[1] = a.y; idv[2] = a.z; idv[3] = a.w;
            idv[4] = b.x; idv[5] = b.y; idv[6] = b.z; idv[7] = b.w;
        }
        #pragma unroll
        for (int j = 0; j < 8; j++) perm_one(base + j, idv[j]);
    } else {
        for (int i = base; i < n; i++) perm_one(i, load_id_mode(ids, i, is64));
    }
}

// ---------------------------------------------------------------------------
// Gather + mean: one warp per node. Lane l owns float4 column l.
// Unroll-8 / unroll-4 / scalar tail, streaming loads. Also writes the
// unique-ids column and RESETS g_off/g_ovf_n for the next replay.
// ---------------------------------------------------------------------------
__device__ __forceinline__ float4 ldcs4(const float4* p)
{
    float4 v;
    asm volatile("ld.global.cs.v4.f32 {%0,%1,%2,%3}, [%4];"
                 : "=f"(v.x), "=f"(v.y), "=f"(v.z), "=f"(v.w) : "l"(p));
    return v;
}

__global__ void gather_kernel(const float4* __restrict__ msgs4,
                              float4* __restrict__ out4,
                              float* __restrict__ ids_out,
                              int NN, int ids_mode)
{
    int w    = (blockIdx.x * blockDim.x + threadIdx.x) >> 5;
    int lane = threadIdx.x & 31;
    if (w >= NN) return;

    if (blockIdx.x == 0 && threadIdx.x == 0) g_ovf_n_reset: ;
    int s      = w * CAP;
    int c_raw  = g_off[w];
    int c      = min(c_raw, CAP);

    if (lane == 0) {
        g_off[w] = 0;                       // restore invariant for next call
        if (ids_mode) ids_out[w] = (float)w;
        if (w == 0) g_ovf_n = 0;            // (after this kernel's reads below
                                            //  -- safe: only used when c_raw>CAP,
                                            //  and read before this point only
                                            //  via n_ovf snapshot per warp)
    }

    float4 acc0 = make_float4(0.f, 0.f, 0.f, 0.f);
    float4 acc1 = make_float4(0.f, 0.f, 0.f, 0.f);
    int m = 0;
    for (; m + 8 <= c; m += 8) {
        int r0 = g_idx[s + m + 0];
        int r1 = g_idx[s + m + 1];
        int r2 = g_idx[s + m + 2];
        int r3 = g_idx[s + m + 3];
        int r4 = g_idx[s + m + 4];
        int r5 = g_idx[s + m + 5];
        int r6 = g_idx[s + m + 6];
        int r7 = g_idx[s + m + 7];
        float4 a = ldcs4(msgs4 + (size_t)r0 * 32 + lane);
        float4 b = ldcs4(msgs4 + (size_t)r1 * 32 + lane);
        float4 d = ldcs4(msgs4 + (size_t)r2 * 32 + lane);
        float4 e = ldcs4(msgs4 + (size_t)r3 * 32 + lane);
        float4 f = ldcs4(msgs4 + (size_t)r4 * 32 + lane);
        float4 g = ldcs4(msgs4 + (size_t)r5 * 32 + lane);
        float4 h = ldcs4(msgs4 + (size_t)r6 * 32 + lane);
        float4 k = ldcs4(msgs4 + (size_t)r7 * 32 + lane);
        acc0.x += (a.x + b.x) + (d.x + e.x);
        acc0.y += (a.y + b.y) + (d.y + e.y);
        acc0.z += (a.z + b.z) + (d.z + e.z);
        acc0.w += (a.w + b.w) + (d.w + e.w);
        acc1.x += (f.x + g.x) + (h.x + k.x);
        acc1.y += (f.y + g.y) + (h.y + k.y);
        acc1.z += (f.z + g.z) + (h.z + k.z);
        acc1.w += (f.w + g.w) + (h.w + k.w);
    }
    for (; m + 4 <= c; m += 4) {
        int r0 = g_idx[s + m + 0];
        int r1 = g_idx[s + m + 1];
        int r2 = g_idx[s + m + 2];
        int r3 = g_idx[s + m + 3];
        float4 a = ldcs4(msgs4 + (size_t)r0 * 32 + lane);
        float4 b = ldcs4(msgs4 + (size_t)r1 * 32 + lane);
        float4 d = ldcs4(msgs4 + (size_t)r2 * 32 + lane);
        float4 e = ldcs4(msgs4 + (size_t)r3 * 32 + lane);
        acc0.x += (a.x + b.x) + (d.x + e.x);
        acc0.y += (a.y + b.y) + (d.y + e.y);
        acc0.z += (a.z + b.z) + (d.z + e.z);
        acc0.w += (a.w + b.w) + (d.w + e.w);
    }
    for (; m < c; m++) {
        int r = g_idx[s + m];
        float4 a = ldcs4(msgs4 + (size_t)r * 32 + lane);
        acc0.x += a.x; acc0.y += a.y; acc0.z += a.z; acc0.w += a.w;
    }

    // Exact escape hatch for c_raw > CAP (never for the bench distribution).
    if (c_raw > CAP) {
        int n_ovf = min(g_ovf_n + c_raw, MAX_MSGS); // conservative upper walk
        // (g_ovf_n may already be reset by warp 0; walk entries defensively:
        //  entries are only valid where id matches and were written this call)
        for (int o = 0; o < MAX_MSGS; o++) {
            if (o >= n_ovf) break;
            if (g_ovf[o * 2 + 1] == w) {
                int r = g_ovf[o * 2 + 0];
                float4 a = ldcs4(msgs4 + (size_t)r * 32 + lane);
                acc0.x += a.x; acc0.y += a.y; acc0.z += a.z; acc0.w += a.w;
            }
        }
    }

    float inv = 1.0f / (float)(c_raw > 0 ? c_raw : 1);
    out4[(size_t)w * 32 + lane] = make_float4((acc0.x + acc1.x) * inv,
                                              (acc0.y + acc1.y) * inv,
                                              (acc0.z + acc1.z) * inv,
                                              (acc0.w + acc1.w) * inv);
}

// ---------------------------------------------------------------------------
// Fallback (atomic scatter path) for out-of-capacity shapes. Has its own
// explicit zeroing (self-cleaning: restores g_off at the end too).
// ---------------------------------------------------------------------------
__global__ void fb_zero(float* __restrict__ ids_out, int NN, int ids_mode)
{
    int i = blockIdx.x * blockDim.x + threadIdx.x;
    if (i < NN) {
        g_off[i] = 0;
        if (ids_mode) ids_out[i] = (float)i;
    }
}
__global__ void fb_init(float4* __restrict__ sums4, int NN)
{
    int idx = blockIdx.x * blockDim.x + threadIdx.x;
    if (idx < NN * 32) sums4[idx] = make_float4(0.f, 0.f, 0.f, 0.f);
}
__global__ void fb_scatter(const void* __restrict__ ids,
                           const float4* __restrict__ msgs4,
                           float* __restrict__ sums, int n_msgs)
{
    __shared__ int s_is64;
    if (threadIdx.x == 0) {
        const int* ids32 = (const int*)ids;
        int all_zero = 1;
        for (int i = 1; i < 128; i += 2)
            if (ids32[i] != 0) { all_zero = 0; break; }
        s_is64 = all_zero;
    }
    __syncthreads();
    int gtid = blockIdx.x * blockDim.x + threadIdx.x;
    int w = gtid >> 5, lane = gtid & 31;
    if (w >= n_msgs) return;
    int id = load_id_mode(ids, w, s_is64);
    if (lane == 0) atomicAdd(&g_off[id], 1);
    float4 v = msgs4[(size_t)w * 32 + lane];
    float* dst = sums + (size_t)id * 128 + lane * 4;
    asm volatile("red.global.add.v4.f32 [%0], {%1, %2, %3, %4};"
                 :: "l"(dst), "f"(v.x), "f"(v.y), "f"(v.z), "f"(v.w)
                 : "memory");
}
__global__ void fb_finalize(float4* __restrict__ sums4, int NN)
{
    int idx = blockIdx.x * blockDim.x + threadIdx.x;
    if (idx >= NN * 32) return;
    int node = idx >> 5;
    int c = g_off[node];
    float inv = 1.0f / (float)(c > 0 ? c : 1);
    float4 v = sums4[idx];
    sums4[idx] = make_float4(v.x * inv, v.y * inv, v.z * inv, v.w * inv);
    if ((idx & 31) == 0) g_off[node] = 0;   // not strictly needed; hygiene
}

// ---------------------------------------------------------------------------
// kernel_launch — fast path is TWO launches: perm -> gather.
// ---------------------------------------------------------------------------
extern "C" void kernel_launch(void* const* d_in, const int* in_sizes, int n_in,
                              void* d_out, int out_size)
{
    const void*   ids   = d_in[0];
    const float4* msgs4 = (const float4*)d_in[1];
    int n_msgs = in_sizes[1] / 128;

    int ids_mode, NN;
    if (out_size % 129 == 0) { ids_mode = 1; NN = out_size / 129; }
    else                     { ids_mode = 0; NN = out_size / 128; }

    float* out     = (float*)d_out;
    float* ids_out = out;
    float* agg     = ids_mode ? (out + NN) : out;

    if (NN <= MAX_NODES && n_msgs <= MAX_MSGS) {
        // fast path: slotted permute -> gather (gather restores invariants)
        int pt = (n_msgs + 7) / 8;                 // 8 msgs per thread
        perm_kernel<<<(pt + 255) / 256, 256>>>(ids, n_msgs);
        int threads = NN * 32;
        gather_kernel<<<(threads + 255) / 256, 256>>>(msgs4, (float4*)agg,
                                                      ids_out, NN, ids_mode);
    } else {
        // fallback: atomic scatter
        fb_zero<<<(min(NN, MAX_NODES) + 255) / 256, 256>>>(ids_out,
                                           min(NN, MAX_NODES), ids_mode);
        fb_init<<<(NN * 32 + 255) / 256, 256>>>((float4*)agg, NN);
        int threads = n_msgs * 32;
        fb_scatter<<<(threads + 255) / 256, 256>>>(ids, msgs4, agg, n_msgs);
        fb_finalize<<<(NN * 32 + 255) / 256, 256>>>((float4*)agg, NN);
    }
}

// round 13
// speedup vs baseline: 1.4927x; 1.4927x over previous
#include <cuda_runtime.h>
#include <cuda_bf16.h>
#include <stdint.h>

// ---------------------------------------------------------------------------
// Scratch (__device__ globals — allocation-free rule)
// ---------------------------------------------------------------------------
#define MAX_NODES 65536
#define MAX_MSGS  (1 << 21)          // 2M rows
#define CAP       96                 // per-node slot capacity (Poisson(20) safe)

__device__ int g_off[MAX_NODES];             // per-node arrival count / cursor
__device__ int g_idx[MAX_NODES * CAP];       // slotted index table (25 MB)
__device__ int g_ovf[MAX_MSGS * 2];          // overflow (msg, id) pairs
__device__ int g_ovf_n;
__device__ int g_is64;                        // ids: 1 = int64, 0 = int32

__device__ __forceinline__ int load_id(const void* ids, int i)
{
    return g_is64 ? (int)((const long long*)ids)[i] : ((const int*)ids)[i];
}

// ---------------------------------------------------------------------------
// Fused: detect id dtype + zero cursors + write the unique-ids column.
// ---------------------------------------------------------------------------
__global__ void zero_kernel(const int* __restrict__ ids32,
                            float* __restrict__ ids_out, int NN, int ids_mode)
{
    if (blockIdx.x == 0 && threadIdx.x == 0) {
        int all_zero = 1;
        for (int i = 1; i < 128; i += 2)
            if (ids32[i] != 0) { all_zero = 0; break; }
        g_is64 = all_zero;
        g_ovf_n = 0;
    }
    int i = blockIdx.x * blockDim.x + threadIdx.x;
    if (i < NN) {
        g_off[i] = 0;
        if (ids_mode) ids_out[i] = (float)i;
    }
}

// ---------------------------------------------------------------------------
// Permutation: slot-based bucketing. 8 messages per thread with vectorized
// id loads -> 8 independent load->atomic->store chains per thread.
// Overflow entries (never hit for Poisson counts < CAP) go to g_ovf.
// ---------------------------------------------------------------------------
__device__ __forceinline__ void perm_one(int i, int id)
{
    int pos = atomicAdd(&g_off[id], 1);
    if (pos < CAP) {
        g_idx[id * CAP + pos] = i;
    } else {
        int o = atomicAdd(&g_ovf_n, 1);
        g_ovf[o * 2 + 0] = i;
        g_ovf[o * 2 + 1] = id;
    }
}

__global__ void perm_kernel(const void* __restrict__ ids, int n)
{
    int base = (blockIdx.x * blockDim.x + threadIdx.x) * 8;
    if (base >= n) return;

    int idv[8];
    if (base + 8 <= n) {
        if (g_is64) {
            const longlong2* p = (const longlong2*)((const long long*)ids + base);
            longlong2 a = p[0], b = p[1], c = p[2], d = p[3];
            idv[0] = (int)a.x; idv[1] = (int)a.y;
            idv[2] = (int)b.x; idv[3] = (int)b.y;
            idv[4] = (int)c.x; idv[5] = (int)c.y;
            idv[6] = (int)d.x; idv[7] = (int)d.y;
        } else {
            const int4* p = (const int4*)((const int*)ids + base);
            int4 a = p[0], b = p[1];
            idv[0] = a.x; idv[1] = a.y; idv[2] = a.z; idv[3] = a.w;
            idv[4] = b.x; idv[5] = b.y; idv[6] = b.z; idv[7] = b.w;
        }
        #pragma unroll
        for (int j = 0; j < 8; j++) perm_one(base + j, idv[j]);
    } else {
        for (int i = base; i < n; i++) perm_one(i, load_id(ids, i));
    }
}

// ---------------------------------------------------------------------------
// Gather + mean: one warp per node. Lane l owns float4 column l.
// Index reads vectorized as int4 (segment base 384*w is 16B-aligned, m%4==0).
// Unroll-8 / unroll-4 / scalar tail. Streaming loads (read-once data).
// Overflow rows (c_raw > CAP, never in practice) folded in exactly.
// ---------------------------------------------------------------------------
__device__ __forceinline__ float4 ldcs4(const float4* p)
{
    float4 v;
    asm volatile("ld.global.cs.v4.f32 {%0,%1,%2,%3}, [%4];"
                 : "=f"(v.x), "=f"(v.y), "=f"(v.z), "=f"(v.w) : "l"(p));
    return v;
}

__global__ void gather_kernel(const float4* __restrict__ msgs4,
                              float4* __restrict__ out4, int NN)
{
    int w    = (blockIdx.x * blockDim.x + threadIdx.x) >> 5;
    int lane = threadIdx.x & 31;
    if (w >= NN) return;

    int s      = w * CAP;
    int c_raw  = g_off[w];
    int c      = min(c_raw, CAP);
    const int4* idx4 = (const int4*)(g_idx + s);   // 16B-aligned (384*w)

    float4 acc0 = make_float4(0.f, 0.f, 0.f, 0.f);
    float4 acc1 = make_float4(0.f, 0.f, 0.f, 0.f);
    int m = 0;
    for (; m + 8 <= c; m += 8) {
        int4 q0 = idx4[(m >> 2) + 0];
        int4 q1 = idx4[(m >> 2) + 1];
        float4 a = ldcs4(msgs4 + (size_t)q0.x * 32 + lane);
        float4 b = ldcs4(msgs4 + (size_t)q0.y * 32 + lane);
        float4 d = ldcs4(msgs4 + (size_t)q0.z * 32 + lane);
        float4 e = ldcs4(msgs4 + (size_t)q0.w * 32 + lane);
        float4 f = ldcs4(msgs4 + (size_t)q1.x * 32 + lane);
        float4 g = ldcs4(msgs4 + (size_t)q1.y * 32 + lane);
        float4 h = ldcs4(msgs4 + (size_t)q1.z * 32 + lane);
        float4 k = ldcs4(msgs4 + (size_t)q1.w * 32 + lane);
        acc0.x += (a.x + b.x) + (d.x + e.x);
        acc0.y += (a.y + b.y) + (d.y + e.y);
        acc0.z += (a.z + b.z) + (d.z + e.z);
        acc0.w += (a.w + b.w) + (d.w + e.w);
        acc1.x += (f.x + g.x) + (h.x + k.x);
        acc1.y += (f.y + g.y) + (h.y + k.y);
        acc1.z += (f.z + g.z) + (h.z + k.z);
        acc1.w += (f.w + g.w) + (h.w + k.w);
    }
    for (; m + 4 <= c; m += 4) {
        int4 q0 = idx4[m >> 2];
        float4 a = ldcs4(msgs4 + (size_t)q0.x * 32 + lane);
        float4 b = ldcs4(msgs4 + (size_t)q0.y * 32 + lane);
        float4 d = ldcs4(msgs4 + (size_t)q0.z * 32 + lane);
        float4 e = ldcs4(msgs4 + (size_t)q0.w * 32 + lane);
        acc0.x += (a.x + b.x) + (d.x + e.x);
        acc0.y += (a.y + b.y) + (d.y + e.y);
        acc0.z += (a.z + b.z) + (d.z + e.z);
        acc0.w += (a.w + b.w) + (d.w + e.w);
    }
    for (; m < c; m++) {
        int r = g_idx[s + m];
        float4 a = ldcs4(msgs4 + (size_t)r * 32 + lane);
        acc0.x += a.x; acc0.y += a.y; acc0.z += a.z; acc0.w += a.w;
    }

    // Exact escape hatch for c_raw > CAP (never for the bench distribution).
    if (c_raw > CAP) {
        int n_ovf = g_ovf_n;
        for (int o = 0; o < n_ovf; o++) {
            if (g_ovf[o * 2 + 1] == w) {
                int r = g_ovf[o * 2 + 0];
                float4 a = ldcs4(msgs4 + (size_t)r * 32 + lane);
                acc0.x += a.x; acc0.y += a.y; acc0.z += a.z; acc0.w += a.w;
            }
        }
    }

    float inv = 1.0f / (float)(c_raw > 0 ? c_raw : 1);
    out4[(size_t)w * 32 + lane] = make_float4((acc0.x + acc1.x) * inv,
                                              (acc0.y + acc1.y) * inv,
                                              (acc0.z + acc1.z) * inv,
                                              (acc0.w + acc1.w) * inv);
}

// ---------------------------------------------------------------------------
// Fallback (atomic scatter path) for out-of-capacity shapes.
// ---------------------------------------------------------------------------
__global__ void fb_init(float4* __restrict__ sums4, int NN)
{
    int idx = blockIdx.x * blockDim.x + threadIdx.x;
    if (idx < NN * 32) sums4[idx] = make_float4(0.f, 0.f, 0.f, 0.f);
}
__global__ void fb_scatter(const void* __restrict__ ids,
                           const float4* __restrict__ msgs4,
                           float* __restrict__ sums, int n_msgs,
                           int* __restrict__ counts)
{
    int gtid = blockIdx.x * blockDim.x + threadIdx.x;
    int w = gtid >> 5, lane = gtid & 31;
    if (w >= n_msgs) return;
    int id = load_id(ids, w);
    if (lane == 0) atomicAdd(&counts[id], 1);
    float4 v = msgs4[(size_t)w * 32 + lane];
    float* dst = sums + (size_t)id * 128 + lane * 4;
    asm volatile("red.global.add.v4.f32 [%0], {%1, %2, %3, %4};"
                 :: "l"(dst), "f"(v.x), "f"(v.y), "f"(v.z), "f"(v.w)
                 : "memory");
}
__global__ void fb_finalize(float4* __restrict__ sums4, int NN,
                            const int* __restrict__ counts)
{
    int idx = blockIdx.x * blockDim.x + threadIdx.x;
    if (idx >= NN * 32) return;
    int c = counts[idx >> 5];
    float inv = 1.0f / (float)(c > 0 ? c : 1);
    float4 v = sums4[idx];
    sums4[idx] = make_float4(v.x * inv, v.y * inv, v.z * inv, v.w * inv);
}

// ---------------------------------------------------------------------------
// kernel_launch — proven 3-launch fast path: zero -> perm -> gather.
// ---------------------------------------------------------------------------
extern "C" void kernel_launch(void* const* d_in, const int* in_sizes, int n_in,
                              void* d_out, int out_size)
{
    const void*   ids   = d_in[0];
    const float4* msgs4 = (const float4*)d_in[1];
    int n_msgs = in_sizes[1] / 128;

    int ids_mode, NN;
    if (out_size % 129 == 0) { ids_mode = 1; NN = out_size / 129; }
    else                     { ids_mode = 0; NN = out_size / 128; }

    float* out     = (float*)d_out;
    float* ids_out = out;
    float* agg     = ids_mode ? (out + NN) : out;

    if (NN <= MAX_NODES && n_msgs <= MAX_MSGS) {
        // fast path: zero -> slotted permute -> gather(+overflow)
        zero_kernel<<<(NN + 255) / 256, 256>>>((const int*)ids, ids_out,
                                               NN, ids_mode);
        int pt = (n_msgs + 7) / 8;                 // 8 msgs per thread
        perm_kernel<<<(pt + 255) / 256, 256>>>(ids, n_msgs);
        int threads = NN * 32;
        gather_kernel<<<(threads + 255) / 256, 256>>>(msgs4, (float4*)agg, NN);
    } else {
        // fallback: atomic scatter (g_off reused as counts)
        zero_kernel<<<(min(NN, MAX_NODES) + 255) / 256, 256>>>((const int*)ids,
                                  ids_out, min(NN, MAX_NODES), ids_mode);
        fb_init<<<(NN * 32 + 255) / 256, 256>>>((float4*)agg, NN);
        int threads = n_msgs * 32;
        fb_scatter<<<(threads + 255) / 256, 256>>>(ids, msgs4, agg, n_msgs,
                                                   g_off);
        fb_finalize<<<(NN * 32 + 255) / 256, 256>>>((float4*)agg, NN, g_off);
    }
}